// round 15
// baseline (speedup 1.0000x reference)
#include <cuda_runtime.h>
#include <math.h>

// Problem constants (fixed by setup_inputs): N=16, T=2048, D=2
#define TT 2048
#define LOG2PI_F 1.8378770664093453f
#define LN2F     0.6931471805599453f

__device__ __forceinline__ float ex2f(float x) {
    float r;
    asm("ex2.approx.f32 %0, %1;" : "=f"(r) : "f"(x));
    return r;
}

__device__ __forceinline__ unsigned long long pack2(float x) {
    unsigned long long d;
    asm("mov.b64 %0, {%1, %1};" : "=l"(d) : "f"(x));
    return d;
}

// u01 = xi2 * XS + (yi2 * YS + A)  in packed f32x2; unpack to (u0, u1).
__device__ __forceinline__ void pair_u(unsigned long long A,
                                       unsigned long long XS,
                                       unsigned long long YS,
                                       unsigned long long xi2,
                                       unsigned long long yi2,
                                       float& u0, float& u1) {
    asm("{\n\t"
        ".reg .b64 t;\n\t"
        "fma.rn.f32x2 t, %3, %4, %2;\n\t"
        "fma.rn.f32x2 t, %5, %6, t;\n\t"
        "mov.b64 {%0, %1}, t;\n\t"
        "}"
        : "=f"(u0), "=f"(u1)
        : "l"(A), "l"(yi2), "l"(YS), "l"(xi2), "l"(XS));
}

// ---------------------------------------------------------------------------
// Packed dense sum over j in [lo, hi) (multiples of 4) from SoA smem arrays.
// Per 4 j: 3 LDS.128 + 4 FFMA2 + 4 MUFU + 4 FADD. Low register footprint;
// latency covered by 8 warps/SMSP TLP.
// ---------------------------------------------------------------------------
__device__ __forceinline__ float dense_sum_p(const ulonglong2* __restrict__ A2,
                                             const ulonglong2* __restrict__ X2,
                                             const ulonglong2* __restrict__ Y2,
                                             int lo, int hi,
                                             unsigned long long xi2,
                                             unsigned long long yi2) {
    float s0 = 0.0f, s1 = 0.0f, s2 = 0.0f, s3 = 0.0f;
    for (int g = lo >> 2; g < (hi >> 2); g++) {
        ulonglong2 a = A2[g];
        ulonglong2 x = X2[g];
        ulonglong2 y = Y2[g];
        float u0, u1, u2, u3;
        pair_u(a.x, x.x, y.x, xi2, yi2, u0, u1);
        pair_u(a.y, x.y, y.y, xi2, yi2, u2, u3);
        s0 += ex2f(u0); s1 += ex2f(u1);
        s2 += ex2f(u2); s3 += ex2f(u3);
    }
    return (s0 + s1) + (s2 + s3);
}

// ---------------------------------------------------------------------------
// Fused kernel. Block = (batch n, slice k of 16), 512 threads (16 warps),
// __launch_bounds__(512, 2) -> 2 blocks/SM -> 8 warps/SMSP.
// Tiles: pair0 = (k, 63-k), pair1 = (k+16, 47-k); each pair stream = 2016 j
// split into 8 chunks of 252. Warp w (s = w&3, c = w>>2):
//   c in {0,1} -> pair0 chunk 2s+c ; c in {2,3} -> pair1 chunk 2s+(c-2)
// Tails (31 predicated j): warp m (0..3) does tile m's tail, folded into its
// own sacc slot (each warp's slot is summed exactly once in reduction).
// ---------------------------------------------------------------------------
__global__ void __launch_bounds__(512, 2)
fused_kernel(const float* __restrict__ tim,
             const float* __restrict__ loc,
             const float* __restrict__ mu0_p,
             const float* __restrict__ ls0_p,
             const float* __restrict__ cd_p,
             const float* __restrict__ sls_p,
             float* __restrict__ out) {
    const int b    = blockIdx.x;
    const int n    = b >> 4;               // batch
    const int k    = b & 15;               // slice 0..15
    const int tid  = threadIdx.x;
    const int wid  = tid >> 5;
    const int lane = tid & 31;
    const int s    = wid & 3;              // SMSP id
    const int c    = wid >> 2;             // 0..3

    __shared__ __align__(16) float sA [TT];   // 8KB  A_j
    __shared__ __align__(16) float sxs[TT];   // 8KB  2*h2l*x_j
    __shared__ __align__(16) float sys[TT];   // 8KB  2*h2l*y_j
    __shared__ float  sE[TT];                 // 8KB  E_j -> prefix P_j
    __shared__ float  wtot[16], wbase[16];
    __shared__ float  saccl[16][32];          // warp partial, pair low tile
    __shared__ float  sacch[16][32];          // warp partial, pair high tile

    const float cd  = *cd_p;
    const float sls = *sls_p;
    const float sp  = log1pf(__expf(cd));  // softplus(coeff_decay)
    const float rc2 = 1.0f / (sp * LN2F);
    const float h2l = 0.5f * __expf(-2.0f * sls) / LN2F;

    const float*  __restrict__ timn = tim + n * TT;
    const float2* __restrict__ locv = ((const float2*)loc) + n * TT;

    // ---- Phase 1a: build SoA pack + E ----
#pragma unroll
    for (int t = 0; t < TT / 512; t++) {
        const int j = t * 512 + tid;
        const float  tj = timn[j];
        const float2 xy = locv[j];
        const float c2 = tj * rc2;
        sA [j] = fmaf(-h2l, fmaf(xy.x, xy.x, xy.y * xy.y), c2);
        sxs[j] = 2.0f * h2l * xy.x;
        sys[j] = 2.0f * h2l * xy.y;
        sE [j] = ex2f(c2);
    }
    __syncthreads();

    // ---- Phase 1b: block scan (exclusive prefix of sE, in place) ----
    {
        const int base = tid << 2;
        float e0 = sE[base + 0], e1 = sE[base + 1];
        float e2 = sE[base + 2], e3 = sE[base + 3];
        const float part = (e0 + e1) + (e2 + e3);

        float inc = part;
#pragma unroll
        for (int o = 1; o < 32; o <<= 1) {
            float v = __shfl_up_sync(0xffffffffu, inc, o);
            if (lane >= o) inc += v;
        }
        if (lane == 31) wtot[wid] = inc;
        __syncthreads();
        if (tid < 16) {
            float v = wtot[tid], s2 = v;
#pragma unroll
            for (int o = 1; o < 16; o <<= 1) {
                float u = __shfl_up_sync(0x0000ffffu, s2, o);
                if (tid >= o) s2 += u;
            }
            wbase[tid] = s2 - v;
        }
        __syncthreads();

        float run = wbase[wid] + (inc - part);
        sE[base + 0] = run; run += e0;
        sE[base + 1] = run; run += e1;
        sE[base + 2] = run; run += e2;
        sE[base + 3] = run;
    }
    __syncthreads();

    // ---- Phase 2: dense work (packed, 252 j per warp) ----
    const int pair = (c >> 1);             // 0 or 1
    const int tl   = k + (pair << 4);      // 0..31
    const int th   = 63 - tl;              // 32..63
    const int bnd  = tl << 5;

    const int chunk = (s << 1) + (c & 1);  // 0..7 within the pair stream
    const int lo = chunk * 252;
    const int hi = lo + 252;

    const float2 xyl = locv[(tl << 5) + lane];
    const float2 xyh = locv[(th << 5) + lane];
    const unsigned long long xl2 = pack2(xyl.x), yl2 = pack2(xyl.y);
    const unsigned long long xh2 = pack2(xyh.x), yh2 = pack2(xyh.y);

    const ulonglong2* A2 = (const ulonglong2*)sA;
    const ulonglong2* X2 = (const ulonglong2*)sxs;
    const ulonglong2* Y2 = (const ulonglong2*)sys;

    float suml = 0.0f, sumh = 0.0f;
    {
        const int e1 = (hi < bnd) ? hi : bnd;     // tl segment [lo, e1)
        if (lo < e1) suml = dense_sum_p(A2, X2, Y2, lo, e1, xl2, yl2);
        const int a2 = (lo > bnd) ? lo : bnd;     // th segment [a2, hi)
        if (a2 < hi) sumh = dense_sum_p(A2, X2, Y2, a2 - bnd, hi - bnd, xh2, yh2);
    }

    // Tails: warp m (0..3) does tile m's tail, folded into its own partial.
    // m=0: tile k    (pair0 low;  this warp IS pair0 -> fold into suml)
    // m=1: tile 63-k (pair0 high; this warp IS pair0 -> fold into sumh)
    // m=2: tile k+16 (pair1 low)  -- warp 2 has c=0 (pair0)! So fold via
    //      dedicated slots instead: warps 12..15 have c=3 (pair1); use warp
    //      2/3's OWN pair... simpler: m=2,3 tails folded into warps 8,9
    //      (c=2, pair1). Assign: tail owner warp for tile:
    //        pair0 low  -> warp 0 (c=0) suml
    //        pair0 high -> warp 1 (c=0) sumh
    //        pair1 low  -> warp 8 (c=2) suml
    //        pair1 high -> warp 9 (c=2) sumh
    if (wid == 0 || wid == 1 || wid == 8 || wid == 9) {
        const bool hiTile = (wid & 1);
        const int  pr     = (wid >> 3);    // 0 for wid 0/1, 1 for wid 8/9
        const int  tt     = hiTile ? (63 - (k + (pr << 4))) : (k + (pr << 4));
        const int  base   = tt << 5;
        const float2 xyt  = locv[base + lane];
        float st = 0.0f;
#pragma unroll
        for (int jt = 0; jt < 31; jt++) {
            float u = fmaf(xyt.x, sxs[base + jt],
                      fmaf(xyt.y, sys[base + jt], sA[base + jt]));
            float e = ex2f(u);
            st += (jt < lane) ? e : 0.0f;
        }
        if (hiTile) sumh += st; else suml += st;
    }

    saccl[wid][lane] = suml;
    sacch[wid][lane] = sumh;
    __syncthreads();

    // ---- Phase 3: reduction + epilogue (warps 0..3 -> 4 tiles) ----
    if (wid < 4) {
        const int  pr  = wid >> 1;         // pair
        const bool low = !(wid & 1);
        const int  t_o = low ? (k + (pr << 4)) : (63 - (k + (pr << 4)));
        const int  i   = (t_o << 5) + lane;
        const float2 xyo = locv[(t_o << 5) + lane];

        // contributing warps: c in {2*pr, 2*pr+1}, all s -> w2 = (c<<2)|s
        float S = 0.0f;
#pragma unroll
        for (int ss = 0; ss < 4; ss++) {
#pragma unroll
            for (int cc = 0; cc < 2; cc++) {
                const int w2 = (((pr << 1) + cc) << 2) | ss;
                S += low ? saccl[w2][lane] : sacch[w2][lane];
            }
        }

        float res;
        if (i == 0) {
            const float mu0 = *mu0_p;
            const float ls0 = *ls0_p;
            const float iv  = __expf(-2.0f * ls0);
            const float dx = xyo.x - mu0, dy = xyo.y - mu0;
            res = -0.5f * iv * fmaf(dx, dx, dy * dy) - 2.0f * ls0 - LOG2PI_F;
        } else {
            const float B2 = -h2l * fmaf(xyo.x, xyo.x, xyo.y * xyo.y);
            const float K  = 2.0f * sls + LOG2PI_F;
            res = __logf(S) + LN2F * B2 - K - __logf(sE[i]);
        }
        out[n * TT + i] = res;
    }
}

// ---------------------------------------------------------------------------
extern "C" void kernel_launch(void* const* d_in, const int* in_sizes, int n_in,
                              void* d_out, int out_size) {
    const float* tim  = (const float*)d_in[0];  // (N, T, 1)
    const float* loc  = (const float*)d_in[1];  // (N, T, 2)
    const float* mu0  = (const float*)d_in[2];
    const float* ls0  = (const float*)d_in[3];
    const float* cd   = (const float*)d_in[4];
    const float* sls  = (const float*)d_in[5];
    float* out = (float*)d_out;

    const int N = in_sizes[0] / TT;             // 16

    fused_kernel<<<N * 16, 512>>>(tim, loc, mu0, ls0, cd, sls, out);
}

// round 16
// speedup vs baseline: 1.1555x; 1.1555x over previous
#include <cuda_runtime.h>
#include <math.h>

// Problem constants (fixed by setup_inputs): N=16, T=2048, D=2
#define TT 2048
#define LOG2PI_F 1.8378770664093453f
#define LN2F     0.6931471805599453f

__device__ __forceinline__ float ex2f(float x) {
    float r;
    asm("ex2.approx.f32 %0, %1;" : "=f"(r) : "f"(x));
    return r;
}

__device__ __forceinline__ unsigned long long pack2(float x) {
    unsigned long long d;
    asm("mov.b64 %0, {%1, %1};" : "=l"(d) : "f"(x));
    return d;
}

// u01 = xi2 * XS + (yi2 * YS + A)  in packed f32x2; unpack to (u0, u1).
__device__ __forceinline__ void pair_u(unsigned long long A,
                                       unsigned long long XS,
                                       unsigned long long YS,
                                       unsigned long long xi2,
                                       unsigned long long yi2,
                                       float& u0, float& u1) {
    asm("{\n\t"
        ".reg .b64 t;\n\t"
        "fma.rn.f32x2 t, %3, %4, %2;\n\t"
        "fma.rn.f32x2 t, %5, %6, t;\n\t"
        "mov.b64 {%0, %1}, t;\n\t"
        "}"
        : "=f"(u0), "=f"(u1)
        : "l"(A), "l"(yi2), "l"(YS), "l"(xi2), "l"(XS));
}

// ---------------------------------------------------------------------------
// Packed dense sum over j in [lo, hi) (multiples of 4) from SoA smem arrays.
// 4-j groups, #pragma unroll 4 -> 16 j per unrolled body so LDS addressing
// becomes [Rbase+imm] and loop control amortizes to ~3 slots / 16 j.
// ---------------------------------------------------------------------------
__device__ __forceinline__ float dense_sum_p(const ulonglong2* __restrict__ A2,
                                             const ulonglong2* __restrict__ X2,
                                             const ulonglong2* __restrict__ Y2,
                                             int lo, int hi,
                                             unsigned long long xi2,
                                             unsigned long long yi2) {
    float s0 = 0.0f, s1 = 0.0f, s2 = 0.0f, s3 = 0.0f;
    const int g0 = lo >> 2, g1 = hi >> 2;
#pragma unroll 4
    for (int g = g0; g < g1; g++) {
        ulonglong2 a = A2[g];
        ulonglong2 x = X2[g];
        ulonglong2 y = Y2[g];
        float u0, u1, u2, u3;
        pair_u(a.x, x.x, y.x, xi2, yi2, u0, u1);
        pair_u(a.y, x.y, y.y, xi2, yi2, u2, u3);
        s0 += ex2f(u0); s1 += ex2f(u1);
        s2 += ex2f(u2); s3 += ex2f(u3);
    }
    return (s0 + s1) + (s2 + s3);
}

// ---------------------------------------------------------------------------
// Fused kernel (R14 layout). Block = (batch n, slice k of 8), 512 threads
// (16 warps), minblocks 1 -> 1 block/SM, 4 warps/SMSP.
// Phase 1: build SoA sA/sxs/sys + sE = 2^{c2}; in-place exclusive scan of sE.
// Phase 2: 4 tile pairs (tl = k+8s, th = 63-tl), pair stream (2016 j) split
//   into 4 equal 504-j chunks for warps {s, s+4, s+8, s+12} (all SMSP s).
//   Tails (31 predicated j) on warps 0..7 (2 per SMSP).
// Phase 3: per-tile reduction + epilogue.
// Grid = 16*8 = 128 blocks -> one wave, one block per SM.
// ---------------------------------------------------------------------------
__global__ void __launch_bounds__(512, 1)
fused_kernel(const float* __restrict__ tim,
             const float* __restrict__ loc,
             const float* __restrict__ mu0_p,
             const float* __restrict__ ls0_p,
             const float* __restrict__ cd_p,
             const float* __restrict__ sls_p,
             float* __restrict__ out) {
    const int b    = blockIdx.x;
    const int n    = b >> 3;               // batch
    const int k    = b & 7;                // slice
    const int tid  = threadIdx.x;
    const int wid  = tid >> 5;
    const int lane = tid & 31;
    const int s    = wid & 3;              // pair id == SMSP id
    const int c    = wid >> 2;             // chunk id 0..3

    __shared__ __align__(16) float sA [TT];   // 8KB  A_j
    __shared__ __align__(16) float sxs[TT];   // 8KB  2*h2l*x_j
    __shared__ __align__(16) float sys[TT];   // 8KB  2*h2l*y_j
    __shared__ float  sE[TT];                 // 8KB  E_j -> prefix P_j
    __shared__ float  wtot[16], wbase[16];
    __shared__ float  saccl[16][32];
    __shared__ float  sacch[16][32];

    const float cd  = *cd_p;
    const float sls = *sls_p;
    const float sp  = log1pf(__expf(cd));  // softplus(coeff_decay)
    const float rc2 = 1.0f / (sp * LN2F);
    const float h2l = 0.5f * __expf(-2.0f * sls) / LN2F;

    const float*  __restrict__ timn = tim + n * TT;
    const float2* __restrict__ locv = ((const float2*)loc) + n * TT;

    // ---- Phase 1a: build SoA pack + E ----
#pragma unroll
    for (int t = 0; t < TT / 512; t++) {
        const int j = t * 512 + tid;
        const float  tj = timn[j];
        const float2 xy = locv[j];
        const float c2 = tj * rc2;
        sA [j] = fmaf(-h2l, fmaf(xy.x, xy.x, xy.y * xy.y), c2);
        sxs[j] = 2.0f * h2l * xy.x;
        sys[j] = 2.0f * h2l * xy.y;
        sE [j] = ex2f(c2);
    }
    __syncthreads();

    // ---- Phase 1b: block scan (exclusive prefix of sE, in place) ----
    {
        const int base = tid << 2;
        float e0 = sE[base + 0], e1 = sE[base + 1];
        float e2 = sE[base + 2], e3 = sE[base + 3];
        const float part = (e0 + e1) + (e2 + e3);

        float inc = part;
#pragma unroll
        for (int o = 1; o < 32; o <<= 1) {
            float v = __shfl_up_sync(0xffffffffu, inc, o);
            if (lane >= o) inc += v;
        }
        if (lane == 31) wtot[wid] = inc;
        __syncthreads();
        if (tid < 16) {
            float v = wtot[tid], s2 = v;
#pragma unroll
            for (int o = 1; o < 16; o <<= 1) {
                float u = __shfl_up_sync(0x0000ffffu, s2, o);
                if (tid >= o) s2 += u;
            }
            wbase[tid] = s2 - v;
        }
        __syncthreads();

        float run = wbase[wid] + (inc - part);
        sE[base + 0] = run; run += e0;
        sE[base + 1] = run; run += e1;
        sE[base + 2] = run; run += e2;
        sE[base + 3] = run;
    }
    __syncthreads();

    // ---- Phase 2: dense work (packed, 504 j per warp) ----
    const int tl  = k + (s << 3);          // 0..31
    const int th  = 63 - tl;               // 32..63
    const int bnd = tl << 5;

    const float2 xyl = locv[(tl << 5) + lane];
    const float2 xyh = locv[(th << 5) + lane];
    const unsigned long long xl2 = pack2(xyl.x), yl2 = pack2(xyl.y);
    const unsigned long long xh2 = pack2(xyh.x), yh2 = pack2(xyh.y);

    const ulonglong2* A2 = (const ulonglong2*)sA;
    const ulonglong2* X2 = (const ulonglong2*)sxs;
    const ulonglong2* Y2 = (const ulonglong2*)sys;

    const int lo = c * 504;
    const int hi = lo + 504;

    float suml = 0.0f, sumh = 0.0f;
    {
        const int e1 = (hi < bnd) ? hi : bnd;     // tl segment [lo, e1)
        if (lo < e1) suml = dense_sum_p(A2, X2, Y2, lo, e1, xl2, yl2);
        const int a2 = (lo > bnd) ? lo : bnd;     // th segment [a2, hi)
        if (a2 < hi) sumh = dense_sum_p(A2, X2, Y2, a2 - bnd, hi - bnd, xh2, yh2);
    }

    // Tails: warps 0..3 -> tile tl; warps 4..7 -> tile th (scalar reads).
    if (wid < 4) {
        const int base = tl << 5;
#pragma unroll
        for (int jt = 0; jt < 31; jt++) {
            float u = fmaf(xyl.x, sxs[base + jt],
                      fmaf(xyl.y, sys[base + jt], sA[base + jt]));
            float e = ex2f(u);
            suml += (jt < lane) ? e : 0.0f;
        }
    } else if (wid < 8) {
        const int base = th << 5;
#pragma unroll
        for (int jt = 0; jt < 31; jt++) {
            float u = fmaf(xyh.x, sxs[base + jt],
                      fmaf(xyh.y, sys[base + jt], sA[base + jt]));
            float e = ex2f(u);
            sumh += (jt < lane) ? e : 0.0f;
        }
    }

    saccl[wid][lane] = suml;
    sacch[wid][lane] = sumh;
    __syncthreads();

    // ---- Phase 3: reduction + epilogue (warps 0..7) ----
    if (wid < 8) {
        const bool low = (wid < 4);
        const int  ss  = wid & 3;
        const int  t_o = low ? (k + (ss << 3)) : (63 - (k + (ss << 3)));
        const int  i   = (t_o << 5) + lane;
        const float2 xyo = locv[(t_o << 5) + lane];

        float S = 0.0f;
#pragma unroll
        for (int m = 0; m < 4; m++)
            S += low ? saccl[ss + (m << 2)][lane] : sacch[ss + (m << 2)][lane];

        float res;
        if (i == 0) {
            const float mu0 = *mu0_p;
            const float ls0 = *ls0_p;
            const float iv  = __expf(-2.0f * ls0);
            const float dx = xyo.x - mu0, dy = xyo.y - mu0;
            res = -0.5f * iv * fmaf(dx, dx, dy * dy) - 2.0f * ls0 - LOG2PI_F;
        } else {
            const float B2 = -h2l * fmaf(xyo.x, xyo.x, xyo.y * xyo.y);
            const float K  = 2.0f * sls + LOG2PI_F;
            res = __logf(S) + LN2F * B2 - K - __logf(sE[i]);
        }
        out[n * TT + i] = res;
    }
}

// ---------------------------------------------------------------------------
extern "C" void kernel_launch(void* const* d_in, const int* in_sizes, int n_in,
                              void* d_out, int out_size) {
    const float* tim  = (const float*)d_in[0];  // (N, T, 1)
    const float* loc  = (const float*)d_in[1];  // (N, T, 2)
    const float* mu0  = (const float*)d_in[2];
    const float* ls0  = (const float*)d_in[3];
    const float* cd   = (const float*)d_in[4];
    const float* sls  = (const float*)d_in[5];
    float* out = (float*)d_out;

    const int N = in_sizes[0] / TT;             // 16

    fused_kernel<<<N * 8, 512>>>(tim, loc, mu0, ls0, cd, sls, out);
}